// round 13
// baseline (speedup 1.0000x reference)
#include <cuda_runtime.h>
#include <math.h>
#include <stdint.h>

// Problem dims (fixed by the reference)
#define NB 8192   // batch
#define NE 256    // embedding
#define NH 4096   // hidden
#define BN_EPS 1e-5f

// ---------------------------------------------------------------------------
// Scratch (device globals: allocation-free)
// ---------------------------------------------------------------------------
__device__ float g_H[2][NB * NH];          // 256 MB: pre-BN hidden per view
__device__ float g_Q[2][NB * NE];          // 16 MB: predictor outputs
__device__ float g_psum[2][64][NH];        // per-128-rowblock partial col sums
__device__ float g_psumsq[2][64][NH];
__device__ float g_scale[2][NH];
__device__ float g_shift[2][NH];
__device__ float g_inorm[4][NB];           // inv row norms: p1,p2,q1,q2
__device__ float g_VT[2][NE * NB];         // VT[0]=q2n^T, VT[1]=q1n^T  [E][B]
__device__ float g_Mp[2][16][NE * NE];     // split-K partials of M
__device__ float g_M[2][NE * NE];
__device__ float g_M2[2][NE * NE];
__device__ float g_tp[2][32][4];

// ---------------------------------------------------------------------------
// Baseline-PTX helpers (compute_103-safe: cp.async / ldmatrix / mma.sync)
// ---------------------------------------------------------------------------
__device__ __forceinline__ uint32_t smem_u32(const void* p) {
    uint32_t a;
    asm("{ .reg .u64 t; cvta.to.shared.u64 t, %1; cvt.u32.u64 %0, t; }"
        : "=r"(a) : "l"(p));
    return a;
}

__device__ __forceinline__ void cp16(uint32_t dst, const void* src) {
    asm volatile("cp.async.cg.shared.global [%0], [%1], 16;" :: "r"(dst), "l"(src));
}
#define CP_COMMIT() asm volatile("cp.async.commit_group;" ::: "memory")
#define CP_WAIT0()  asm volatile("cp.async.wait_group 0;" ::: "memory")

__device__ __forceinline__ void ldsm4(uint32_t* r, uint32_t a) {
    asm volatile("ldmatrix.sync.aligned.m8n8.x4.shared.b16 {%0,%1,%2,%3}, [%4];"
                 : "=r"(r[0]), "=r"(r[1]), "=r"(r[2]), "=r"(r[3]) : "r"(a));
}

__device__ __forceinline__ void mma8(float* d, const uint32_t* a, const uint32_t* b) {
    asm volatile(
        "mma.sync.aligned.m16n8k8.row.col.f32.tf32.tf32.f32 "
        "{%0,%1,%2,%3}, {%4,%5,%6,%7}, {%8,%9}, {%0,%1,%2,%3};"
        : "+f"(d[0]), "+f"(d[1]), "+f"(d[2]), "+f"(d[3])
        : "r"(a[0]), "r"(a[1]), "r"(a[2]), "r"(a[3]), "r"(b[0]), "r"(b[1]));
}

#define ASWZ(row, colb) ((row) * 128 + ((colb) ^ (((row) & 7) << 4)))

// ---- New wide-tile layout (gemm1/gemm2): CTA 128m x 256n, warp 64x64 ----
// A: 128 rows x 128B swizzled, double buffered (16 KB each)
// B: 32 k-rows x 1056B pitch (256 n-floats + 32B pad; 264 % 32 == 8 -> the
//    4-row x 8-col LDS.32 pattern covers all 32 banks), double buffered
#define W_SA0 0
#define W_SA1 16384
#define W_SB0 32768
#define W_SB1 (32768 + 33792)
#define W_TOT (W_SB1 + 33792)
#define W_DYN (W_TOT + 128)
#define W_BP  1056

// ---- Old narrow layout (gemmM keeps the proven 128x128 config) ----
#define SA0 0
#define SA1 16384
#define SB0 32768
#define SB1 50176
#define SMEM_TOT 67584
#define SMEM_DYN (SMEM_TOT + 128)
#define BPITCH 544

// ---------------------------------------------------------------------------
// GEMM1: H[v] = z_v @ W1  (8192x256 @ 256x4096), tf32 mma.sync
// CTA 128x256, warp 64x64, fused BN partial column sums in epilogue.
// grid (NH/256=16, NB/128=64, 2), 256 threads
// ---------------------------------------------------------------------------
__global__ __launch_bounds__(256) void k_gemm1(const float* __restrict__ z1,
                                               const float* __restrict__ z2,
                                               const float* __restrict__ W1) {
    extern __shared__ char smraw[];
    uint32_t sb0 = smem_u32(smraw);
    uint32_t pad = (128u - (sb0 & 127u)) & 127u;
    char* sm = smraw + pad;
    uint32_t sb = sb0 + pad;

    const int v = blockIdx.z;
    const float* __restrict__ A = v ? z2 : z1;
    const int m0 = blockIdx.y * 128, n0 = blockIdx.x * 256;
    const int tid = threadIdx.x;
    const int lane = tid & 31, wid = tid >> 5;
    const int gid = lane >> 2, tig = lane & 3;
    const int wm = (wid >> 2) * 64;      // 2 m-warp groups
    const int wn = (wid & 3) * 64;       // 4 n-warp groups

    const int q = lane >> 3, r7 = lane & 7;
    const int a_ld_row = wm + (q & 1) * 8 + r7;
    const uint32_t a_xor = (uint32_t)(r7 << 4);
    const int a_cb = (q >> 1) * 16;

    float d[4][8][4] = {};

    auto loadA = [&](int c, int buf) {
        uint32_t base = sb + (buf ? W_SA1 : W_SA0);
        const float* Ab = A + (size_t)m0 * NE + c * 32;
#pragma unroll
        for (int i = 0; i < 4; i++) {
            int e = i * 256 + tid;
            int row = e >> 3, colb = (e & 7) * 16;
            cp16(base + ASWZ(row, colb), Ab + (size_t)row * NE + (colb >> 2));
        }
    };
    auto loadB = [&](int c, int buf) {
        uint32_t base = sb + (buf ? W_SB1 : W_SB0);
        const float* Bb = W1 + (size_t)(c * 32) * NH + n0;
#pragma unroll
        for (int i = 0; i < 8; i++) {
            int e = i * 256 + tid;
            int kr = e >> 6, colb = (e & 63) * 16;
            cp16(base + kr * W_BP + colb, Bb + (size_t)kr * NH + (colb >> 2));
        }
    };

    loadA(0, 0); loadB(0, 0); CP_COMMIT(); CP_WAIT0();
    __syncthreads();

    const int NC = NE / 32;  // 8
    for (int c = 0; c < NC; c++) {
        int cur = c & 1;
        if (c + 1 < NC) { loadA(c + 1, cur ^ 1); loadB(c + 1, cur ^ 1); CP_COMMIT(); }
        uint32_t abase = sb + (cur ? W_SA1 : W_SA0);
        int bbo = (cur ? W_SB1 : W_SB0);
#pragma unroll
        for (int s = 0; s < 4; s++) {
            uint32_t afr[4][4];
#pragma unroll
            for (int mt = 0; mt < 4; mt++) {
                int row = a_ld_row + mt * 16;
                uint32_t colb = (uint32_t)(s * 32 + a_cb) ^ a_xor;
                ldsm4(afr[mt], abase + row * 128 + colb);
            }
            uint32_t bfr[8][2];
#pragma unroll
            for (int nt = 0; nt < 8; nt++) {
                int bo = bbo + (s * 8 + tig) * W_BP + (wn + nt * 8 + gid) * 4;
                bfr[nt][0] = *(const uint32_t*)(sm + bo);
                bfr[nt][1] = *(const uint32_t*)(sm + bo + 4 * W_BP);
            }
#pragma unroll
            for (int mt = 0; mt < 4; mt++)
#pragma unroll
                for (int nt = 0; nt < 8; nt++)
                    mma8(d[mt][nt], afr[mt], bfr[nt]);
        }
        if (c + 1 < NC) CP_WAIT0();
        __syncthreads();
    }

    // epilogue: store C
    float* C = g_H[v];
#pragma unroll
    for (int mt = 0; mt < 4; mt++) {
        int r0 = m0 + wm + mt * 16 + gid;
#pragma unroll
        for (int nt = 0; nt < 8; nt++) {
            int cc = n0 + wn + nt * 8 + 2 * tig;
            *(float2*)&C[(size_t)r0 * NH + cc] = make_float2(d[mt][nt][0], d[mt][nt][1]);
            *(float2*)&C[(size_t)(r0 + 8) * NH + cc] = make_float2(d[mt][nt][2], d[mt][nt][3]);
        }
    }

    // fused BN partial sums over this block's 128 rows (cols n0..n0+255)
    float s[8][2], ss[8][2];
#pragma unroll
    for (int nt = 0; nt < 8; nt++)
#pragma unroll
        for (int j = 0; j < 2; j++) {
            float a = 0.f, b = 0.f;
#pragma unroll
            for (int mt = 0; mt < 4; mt++) {
                float x = d[mt][nt][j], y = d[mt][nt][2 + j];
                a += x + y;
                b = fmaf(x, x, fmaf(y, y, b));
            }
            s[nt][j] = a; ss[nt][j] = b;
        }
#pragma unroll
    for (int o = 4; o <= 16; o <<= 1) {
#pragma unroll
        for (int nt = 0; nt < 8; nt++)
#pragma unroll
            for (int j = 0; j < 2; j++) {
                s[nt][j] += __shfl_xor_sync(0xffffffffu, s[nt][j], o);
                ss[nt][j] += __shfl_xor_sync(0xffffffffu, ss[nt][j], o);
            }
    }
    __syncthreads();  // done with A/B buffers; reuse for reduction
    float* red = (float*)sm;  // [s|ss][2 m-groups][256 cols] = 1024 floats
    int wgrp = wid >> 2;
    if (gid == 0) {
#pragma unroll
        for (int nt = 0; nt < 8; nt++)
#pragma unroll
            for (int j = 0; j < 2; j++) {
                int col = wn + nt * 8 + 2 * tig + j;
                red[wgrp * 256 + col] = s[nt][j];
                red[512 + wgrp * 256 + col] = ss[nt][j];
            }
    }
    __syncthreads();
    {
        int col = tid;  // 0..255
        g_psum[v][blockIdx.y][n0 + col]   = red[col] + red[256 + col];
        g_psumsq[v][blockIdx.y][n0 + col] = red[512 + col] + red[768 + col];
    }
}

// Finalize BN: scale/shift per (view, hidden unit). grid 32 x 256
__global__ void k_bnfin(const float* __restrict__ gamma,
                        const float* __restrict__ beta) {
    int i = blockIdx.x * 256 + threadIdx.x;
    int v = i >> 12;
    int h = i & (NH - 1);
    float s = 0.f, s2 = 0.f;
#pragma unroll
    for (int b = 0; b < 64; b++) { s += g_psum[v][b][h]; s2 += g_psumsq[v][b][h]; }
    float mu = s * (1.f / NB);
    float var = s2 * (1.f / NB) - mu * mu;
    float scl = rsqrtf(var + BN_EPS) * gamma[h];
    g_scale[v][h] = scl;
    g_shift[v][h] = fmaf(-mu, scl, beta[h]);
}

// ---------------------------------------------------------------------------
// GEMM2: Q[v] = relu(bn(H[v])) @ W2 + b2  (8192x4096 @ 4096x256)
// CTA 128x256 (full N in one CTA), warp 64x64. A transformed on LDG->STS path.
// grid (1, 64, 2), 256 threads
// ---------------------------------------------------------------------------
__global__ __launch_bounds__(256) void k_gemm2(const float* __restrict__ W2,
                                               const float* __restrict__ b2) {
    extern __shared__ char smraw[];
    uint32_t sb0 = smem_u32(smraw);
    uint32_t pad = (128u - (sb0 & 127u)) & 127u;
    char* sm = smraw + pad;
    uint32_t sb = sb0 + pad;

    const int v = blockIdx.z;
    const float* __restrict__ A = g_H[v];
    const float* __restrict__ sc = g_scale[v];
    const float* __restrict__ sh = g_shift[v];
    const int m0 = blockIdx.y * 128;
    const int tid = threadIdx.x;
    const int lane = tid & 31, wid = tid >> 5;
    const int gid = lane >> 2, tig = lane & 3;
    const int wm = (wid >> 2) * 64, wn = (wid & 3) * 64;
    const int q = lane >> 3, r7 = lane & 7;
    const int a_ld_row = wm + (q & 1) * 8 + r7;
    const uint32_t a_xor = (uint32_t)(r7 << 4);
    const int a_cb = (q >> 1) * 16;

    float d[4][8][4] = {};
    float4 areg[4];

    auto ldgA = [&](int c) {
        const float* Ab = A + (size_t)m0 * NH + c * 32;
#pragma unroll
        for (int i = 0; i < 4; i++) {
            int e = i * 256 + tid;
            int row = e >> 3, kc = (e & 7) * 4;
            areg[i] = *(const float4*)(Ab + (size_t)row * NH + kc);
        }
    };
    auto stsA = [&](int c, int buf) {
        char* base = sm + (buf ? W_SA1 : W_SA0);
#pragma unroll
        for (int i = 0; i < 4; i++) {
            int e = i * 256 + tid;
            int row = e >> 3, kc = (e & 7) * 4;
            float4 s4 = *(const float4*)(sc + c * 32 + kc);
            float4 t4 = *(const float4*)(sh + c * 32 + kc);
            float4 a;
            a.x = fmaxf(fmaf(areg[i].x, s4.x, t4.x), 0.f);
            a.y = fmaxf(fmaf(areg[i].y, s4.y, t4.y), 0.f);
            a.z = fmaxf(fmaf(areg[i].z, s4.z, t4.z), 0.f);
            a.w = fmaxf(fmaf(areg[i].w, s4.w, t4.w), 0.f);
            *(float4*)(base + ASWZ(row, kc * 4)) = a;
        }
    };
    auto loadB = [&](int c, int buf) {
        uint32_t base = sb + (buf ? W_SB1 : W_SB0);
        const float* Bb = W2 + (size_t)(c * 32) * NE;
#pragma unroll
        for (int i = 0; i < 8; i++) {
            int e = i * 256 + tid;
            int kr = e >> 6, colb = (e & 63) * 16;
            cp16(base + kr * W_BP + colb, Bb + (size_t)kr * NE + (colb >> 2));
        }
    };

    ldgA(0); loadB(0, 0); CP_COMMIT();
    stsA(0, 0);
    CP_WAIT0();
    __syncthreads();

    const int NC = NH / 32;  // 128
    for (int c = 0; c < NC; c++) {
        int cur = c & 1;
        if (c + 1 < NC) { ldgA(c + 1); loadB(c + 1, cur ^ 1); CP_COMMIT(); }
        uint32_t abase = sb + (cur ? W_SA1 : W_SA0);
        int bbo = (cur ? W_SB1 : W_SB0);
#pragma unroll
        for (int s = 0; s < 4; s++) {
            uint32_t afr[4][4];
#pragma unroll
            for (int mt = 0; mt < 4; mt++) {
                int row = a_ld_row + mt * 16;
                uint32_t colb = (uint32_t)(s * 32 + a_cb) ^ a_xor;
                ldsm4(afr[mt], abase + row * 128 + colb);
            }
            uint32_t bfr[8][2];
#pragma unroll
            for (int nt = 0; nt < 8; nt++) {
                int bo = bbo + (s * 8 + tig) * W_BP + (wn + nt * 8 + gid) * 4;
                bfr[nt][0] = *(const uint32_t*)(sm + bo);
                bfr[nt][1] = *(const uint32_t*)(sm + bo + 4 * W_BP);
            }
#pragma unroll
            for (int mt = 0; mt < 4; mt++)
#pragma unroll
                for (int nt = 0; nt < 8; nt++)
                    mma8(d[mt][nt], afr[mt], bfr[nt]);
        }
        if (c + 1 < NC) { stsA(c + 1, cur ^ 1); CP_WAIT0(); }
        __syncthreads();
    }

    float* C = g_Q[v];
#pragma unroll
    for (int mt = 0; mt < 4; mt++) {
        int r0 = m0 + wm + mt * 16 + gid;
#pragma unroll
        for (int nt = 0; nt < 8; nt++) {
            int cc = wn + nt * 8 + 2 * tig;
            float2 bias = *(const float2*)(b2 + cc);
            *(float2*)&C[(size_t)r0 * NE + cc] =
                make_float2(d[mt][nt][0] + bias.x, d[mt][nt][1] + bias.y);
            *(float2*)&C[(size_t)(r0 + 8) * NE + cc] =
                make_float2(d[mt][nt][2] + bias.x, d[mt][nt][3] + bias.y);
        }
    }
}

// ---------------------------------------------------------------------------
// M-GEMM (split-K): Mp[mec][s][i][j] = sum_{b in slice} v2n^T[i][b] * v1n[b][j]
// Proven 128x128 config. grid (2 j, 2 i, 2*16), K per split = 512
// ---------------------------------------------------------------------------
__global__ __launch_bounds__(256) void k_gemmM(const float* __restrict__ p1,
                                               const float* __restrict__ p2) {
    extern __shared__ char smraw[];
    uint32_t sb0 = smem_u32(smraw);
    uint32_t pad = (128u - (sb0 & 127u)) & 127u;
    char* sm = smraw + pad;
    uint32_t sb = sb0 + pad;

    const int mec = blockIdx.z >> 4;
    const int split = blockIdx.z & 15;
    const float* __restrict__ A = g_VT[mec];
    const float* __restrict__ P = mec ? p2 : p1;
    const float* __restrict__ nrm = g_inorm[mec];
    const int i0 = blockIdx.y * 128, j0 = blockIdx.x * 128;
    const int kbase = split * 512;
    const int tid = threadIdx.x;
    const int lane = tid & 31, wid = tid >> 5;
    const int gid = lane >> 2, tig = lane & 3;
    const int wm = (wid >> 2) * 64, wn = (wid & 3) * 32;
    const int q = lane >> 3, r7 = lane & 7;
    const int a_ld_row = wm + (q & 1) * 8 + r7;
    const uint32_t a_xor = (uint32_t)(r7 << 4);
    const int a_cb = (q >> 1) * 16;

    float d[4][4][4] = {};
    float4 breg[4];
    float bnrm[4];

    auto loadA = [&](int c, int buf) {
        uint32_t base = sb + (buf ? SA1 : SA0);
        const float* Ab = A + (size_t)i0 * NB + kbase + c * 32;
#pragma unroll
        for (int i = 0; i < 4; i++) {
            int e = i * 256 + tid;
            int row = e >> 3, colb = (e & 7) * 16;
            cp16(base + ASWZ(row, colb), Ab + (size_t)row * NB + (colb >> 2));
        }
    };
    auto ldgB = [&](int c) {
#pragma unroll
        for (int i = 0; i < 4; i++) {
            int e = i * 256 + tid;
            int kr = e >> 5, col = (e & 31) * 4;
            int b = kbase + c * 32 + kr;
            breg[i] = *(const float4*)(P + (size_t)b * NE + j0 + col);
            bnrm[i] = nrm[b];
        }
    };
    auto stsB = [&](int buf) {
        char* base = sm + (buf ? SB1 : SB0);
#pragma unroll
        for (int i = 0; i < 4; i++) {
            int e = i * 256 + tid;
            int kr = e >> 5, colb = (e & 31) * 16;
            float n = bnrm[i];
            *(float4*)(base + kr * BPITCH + colb) =
                make_float4(breg[i].x * n, breg[i].y * n, breg[i].z * n, breg[i].w * n);
        }
    };

    ldgB(0); loadA(0, 0); CP_COMMIT();
    stsB(0);
    CP_WAIT0();
    __syncthreads();

    const int NC = 16;  // 512 / 32
    for (int c = 0; c < NC; c++) {
        int cur = c & 1;
        if (c + 1 < NC) { ldgB(c + 1); loadA(c + 1, cur ^ 1); CP_COMMIT(); }
        uint32_t abase = sb + (cur ? SA1 : SA0);
        int bbo = (cur ? SB1 : SB0);
#pragma unroll
        for (int s = 0; s < 4; s++) {
            uint32_t afr[4][4];
#pragma unroll
            for (int mt = 0; mt < 4; mt++) {
                int row = a_ld_row + mt * 16;
                uint32_t colb = (uint32_t)(s * 32 + a_cb) ^ a_xor;
                ldsm4(afr[mt], abase + row * 128 + colb);
            }
            uint32_t bfr[4][2];
#pragma unroll
            for (int nt = 0; nt < 4; nt++) {
                int bo = bbo + (s * 8 + tig) * BPITCH + (wn + nt * 8 + gid) * 4;
                bfr[nt][0] = *(const uint32_t*)(sm + bo);
                bfr[nt][1] = *(const uint32_t*)(sm + bo + 4 * BPITCH);
            }
#pragma unroll
            for (int mt = 0; mt < 4; mt++)
#pragma unroll
                for (int nt = 0; nt < 4; nt++)
                    mma8(d[mt][nt], afr[mt], bfr[nt]);
        }
        if (c + 1 < NC) { stsB(cur ^ 1); CP_WAIT0(); }
        __syncthreads();
    }

    float* O = g_Mp[mec][split];
#pragma unroll
    for (int mt = 0; mt < 4; mt++) {
        int r0 = i0 + wm + mt * 16 + gid;
#pragma unroll
        for (int nt = 0; nt < 4; nt++) {
            int cc = j0 + wn + nt * 8 + 2 * tig;
            *(float2*)&O[(size_t)r0 * NE + cc] = make_float2(d[mt][nt][0], d[mt][nt][1]);
            *(float2*)&O[(size_t)(r0 + 8) * NE + cc] = make_float2(d[mt][nt][2], d[mt][nt][3]);
        }
    }
}

// ---------------------------------------------------------------------------
// Row inverse L2 norms for p1, p2, q1, q2
// ---------------------------------------------------------------------------
__global__ __launch_bounds__(256) void k_norms(const float* __restrict__ p1,
                                               const float* __restrict__ p2) {
    int mat = blockIdx.y;
    const float* X = (mat == 0) ? p1 : (mat == 1) ? p2 : g_Q[mat - 2];
    int row = blockIdx.x * 8 + (threadIdx.x >> 5);
    int lane = threadIdx.x & 31;
    const float* xr = X + (size_t)row * NE;
    float s = 0.f;
#pragma unroll
    for (int j = 0; j < NE; j += 32) {
        float x = xr[j + lane];
        s = fmaf(x, x, s);
    }
#pragma unroll
    for (int o = 16; o; o >>= 1) s += __shfl_xor_sync(0xffffffffu, s, o);
    if (lane == 0) g_inorm[mat][row] = 1.f / fmaxf(sqrtf(s), 1e-12f);
}

// transpose+normalize q2 -> VT[0], q1 -> VT[1]
__global__ __launch_bounds__(256) void k_transnorm() {
    __shared__ float t[32][33];
    int z = blockIdx.z;                 // 0: q2, 1: q1
    const float* X = g_Q[1 - z];
    const float* nrm = g_inorm[3 - z];
    float* O = g_VT[z];
    int bx = blockIdx.x * 32;           // over B
    int by = blockIdx.y * 32;           // over E
    int tx = threadIdx.x & 31, ty = threadIdx.x >> 5;
#pragma unroll
    for (int i = 0; i < 4; i++) {
        int r = bx + ty + 8 * i;
        t[ty + 8 * i][tx] = X[(size_t)r * NE + by + tx] * nrm[r];
    }
    __syncthreads();
#pragma unroll
    for (int i = 0; i < 4; i++)
        O[(size_t)(by + ty + 8 * i) * NB + bx + tx] = t[tx][ty + 8 * i];
}

// Reduce split-K partials and apply 1/lamda_inv. grid (256, 2)
__global__ void k_Mred(const float* __restrict__ plam) {
    int m = blockIdx.y;
    int i = blockIdx.x * 256 + threadIdx.x;
    float inv = 1.f / *plam;
    float s = 0.f;
#pragma unroll
    for (int ks = 0; ks < 16; ks++) s += g_Mp[m][ks][i];
    g_M[m][i] = s * inv;
}

// ---------------------------------------------------------------------------
// M2 = M @ M (256^3), traces, final scalar
// ---------------------------------------------------------------------------
__global__ __launch_bounds__(256) void k_M2() {
    const int m = blockIdx.z;
    const float* M = g_M[m];
    float* O = g_M2[m];
    __shared__ float As[16][64];
    __shared__ float Bs[16][64];
    const int tid = threadIdx.x;
    const int tx = tid & 15, ty = tid >> 4;
    const int i0 = blockIdx.y * 64, j0 = blockIdx.x * 64;
    const int ai = tid >> 2, ak = (tid & 3) * 4;
    const int bk = tid >> 4, bj = (tid & 15) * 4;
    float acc[4][4] = {};
    for (int kb = 0; kb < NE; kb += 16) {
        float4 av = *(const float4*)(M + (i0 + ai) * NE + kb + ak);
        float4 bv = *(const float4*)(M + (kb + bk) * NE + j0 + bj);
        __syncthreads();
        As[ak + 0][ai] = av.x; As[ak + 1][ai] = av.y;
        As[ak + 2][ai] = av.z; As[ak + 3][ai] = av.w;
        *(float4*)&Bs[bk][bj] = bv;
        __syncthreads();
#pragma unroll
        for (int k = 0; k < 16; k++) {
            float a[4], bb[4];
            *(float4*)a = *(const float4*)&As[k][ty * 4];
            *(float4*)bb = *(const float4*)&Bs[k][tx * 4];
#pragma unroll
            for (int ii = 0; ii < 4; ii++)
#pragma unroll
                for (int jj = 0; jj < 4; jj++)
                    acc[ii][jj] = fmaf(a[ii], bb[jj], acc[ii][jj]);
        }
    }
#pragma unroll
    for (int ii = 0; ii < 4; ii++)
#pragma unroll
        for (int jj = 0; jj < 4; jj++)
            O[(i0 + ty * 4 + ii) * NE + j0 + tx * 4 + jj] = acc[ii][jj];
}

__global__ __launch_bounds__(256) void k_traces() {
    const int m = blockIdx.y;
    const float* M = g_M[m];
    const float* M2 = g_M2[m];
    const int tid = threadIdx.x;
    const int idx0 = blockIdx.x * 2048;
    float t1 = 0.f, t2 = 0.f, t3 = 0.f, t4 = 0.f;
    for (int idx = idx0 + tid; idx < idx0 + 2048; idx += 256) {
        int i = idx >> 8, j = idx & 255;
        float mij = M[idx], mji = M[j * NE + i];
        float m2ij = M2[idx], m2ji = M2[j * NE + i];
        if (i == j) t1 += mij;
        t2 = fmaf(mij, mji, t2);
        t3 = fmaf(m2ij, mji, t3);
        t4 = fmaf(m2ij, m2ji, t4);
    }
    __shared__ float red[4][256];
    red[0][tid] = t1; red[1][tid] = t2; red[2][tid] = t3; red[3][tid] = t4;
    __syncthreads();
    for (int s = 128; s > 0; s >>= 1) {
        if (tid < s) {
            red[0][tid] += red[0][tid + s];
            red[1][tid] += red[1][tid + s];
            red[2][tid] += red[2][tid + s];
            red[3][tid] += red[3][tid + s];
        }
        __syncthreads();
    }
    if (tid < 4) g_tp[m][blockIdx.x][tid] = red[tid][0];
}

__global__ void k_final(const float* __restrict__ plam, float* __restrict__ out) {
    float t[2][4];
    for (int m = 0; m < 2; m++)
        for (int c = 0; c < 4; c++) {
            float s = 0.f;
            for (int b = 0; b < 32; b++) s += g_tp[m][b][c];
            t[m][c] = s;
        }
    float s0 = t[0][0] - 0.5f * t[0][1] + (1.f / 3.f) * t[0][2] - 0.25f * t[0][3];
    float s1 = t[1][0] - 0.5f * t[1][1] + (1.f / 3.f) * t[1][2] - 0.25f * t[1][3];
    float loss = (s0 + s1) * 0.5f / (float)NB;
    out[0] = -loss * (*plam);
}

// ---------------------------------------------------------------------------
// Launch
// ---------------------------------------------------------------------------
extern "C" void kernel_launch(void* const* d_in, const int* in_sizes, int n_in,
                              void* d_out, int out_size) {
    const float* z1    = (const float*)d_in[0];
    const float* z2    = (const float*)d_in[1];
    const float* p1    = (const float*)d_in[2];
    const float* p2    = (const float*)d_in[3];
    const float* W1    = (const float*)d_in[4];
    const float* gamma = (const float*)d_in[5];
    const float* beta  = (const float*)d_in[6];
    const float* W2    = (const float*)d_in[7];
    const float* b2    = (const float*)d_in[8];
    const float* plam  = (const float*)d_in[9];
    float* out = (float*)d_out;

    cudaFuncSetAttribute(k_gemm1, cudaFuncAttributeMaxDynamicSharedMemorySize, W_DYN);
    cudaFuncSetAttribute(k_gemm2, cudaFuncAttributeMaxDynamicSharedMemorySize, W_DYN);
    cudaFuncSetAttribute(k_gemmM, cudaFuncAttributeMaxDynamicSharedMemorySize, SMEM_DYN);

    // 1) H = z @ W1 (tf32 mma.sync, 128x256 CTA tile) + fused BN partial stats
    k_gemm1<<<dim3(NH / 256, NB / 128, 2), 256, W_DYN>>>(z1, z2, W1);
    k_bnfin<<<(2 * NH) / 256, 256>>>(gamma, beta);
    // 2) Q = relu(bn(H)) @ W2 + b2 (full-N CTA tile)
    k_gemm2<<<dim3(1, NB / 128, 2), 256, W_DYN>>>(W2, b2);
    // 3) norms + transpose/normalize q's
    k_norms<<<dim3(NB / 8, 4), 256>>>(p1, p2);
    k_transnorm<<<dim3(NB / 32, NE / 32, 2), 256>>>();
    // 4) M via split-K tf32 GEMM + deterministic reduce (applies 1/lamda_inv)
    k_gemmM<<<dim3(NE / 128, NE / 128, 32), 256, SMEM_DYN>>>(p1, p2);
    k_Mred<<<dim3((NE * NE) / 256, 2), 256>>>(plam);
    // 5) M2, traces, final
    k_M2<<<dim3(NE / 64, NE / 64, 2), 256>>>();
    k_traces<<<dim3(32, 2), 256>>>();
    k_final<<<1, 1>>>(plam, out);
}

// round 14
// speedup vs baseline: 1.3821x; 1.3821x over previous
#include <cuda_runtime.h>
#include <cuda_fp16.h>
#include <math.h>
#include <stdint.h>

// Problem dims (fixed by the reference)
#define NB 8192   // batch
#define NE 256    // embedding
#define NH 4096   // hidden
#define BN_EPS 1e-5f

// ---------------------------------------------------------------------------
// Scratch (device globals: allocation-free)
// ---------------------------------------------------------------------------
__device__ float g_H[2][NB * NH];          // 256 MB: pre-BN hidden per view
__device__ float g_Q[2][NB * NE];          // 16 MB: predictor outputs
__device__ float g_psum[2][64][NH];        // per-128-rowblock partial col sums
__device__ float g_psumsq[2][64][NH];
__device__ float g_scale[2][NH];
__device__ float g_shift[2][NH];
__device__ float g_inorm[4][NB];           // inv row norms: p1,p2,q1,q2
__device__ __half g_z16[2][NB * NE];       // fp16 z views
__device__ __half g_W1T16[NH * NE];        // W1^T fp16 [H][E]
__device__ __half g_W2T16[NE * NH];        // W2^T fp16 [E][H]
__device__ __half g_VT16[2][NE * NB];      // VT16[0]=q2n^T, VT16[1]=q1n^T
__device__ __half g_PT16[2][NE * NB];      // PT16[0]=p1n^T, PT16[1]=p2n^T
__device__ float g_Mp[2][16][NE * NE];     // split-K partials of M
__device__ float g_M[2][NE * NE];
__device__ float g_M2[2][NE * NE];
__device__ float g_tp[2][32][4];

// ---------------------------------------------------------------------------
// Baseline-PTX helpers (compute_103-safe: cp.async / ldmatrix / mma.sync)
// ---------------------------------------------------------------------------
__device__ __forceinline__ uint32_t smem_u32(const void* p) {
    uint32_t a;
    asm("{ .reg .u64 t; cvta.to.shared.u64 t, %1; cvt.u32.u64 %0, t; }"
        : "=r"(a) : "l"(p));
    return a;
}

__device__ __forceinline__ void cp16(uint32_t dst, const void* src) {
    asm volatile("cp.async.cg.shared.global [%0], [%1], 16;" :: "r"(dst), "l"(src));
}
#define CP_COMMIT() asm volatile("cp.async.commit_group;" ::: "memory")
#define CP_WAIT0()  asm volatile("cp.async.wait_group 0;" ::: "memory")

__device__ __forceinline__ void ldsm4(uint32_t* r, uint32_t a) {
    asm volatile("ldmatrix.sync.aligned.m8n8.x4.shared.b16 {%0,%1,%2,%3}, [%4];"
                 : "=r"(r[0]), "=r"(r[1]), "=r"(r[2]), "=r"(r[3]) : "r"(a));
}

// fp16 mma with fp32 accumulate (baseline PTX, sm_80-era)
__device__ __forceinline__ void mma16(float* d, const uint32_t* a, const uint32_t* b) {
    asm volatile(
        "mma.sync.aligned.m16n8k16.row.col.f32.f16.f16.f32 "
        "{%0,%1,%2,%3}, {%4,%5,%6,%7}, {%8,%9}, {%0,%1,%2,%3};"
        : "+f"(d[0]), "+f"(d[1]), "+f"(d[2]), "+f"(d[3])
        : "r"(a[0]), "r"(a[1]), "r"(a[2]), "r"(a[3]), "r"(b[0]), "r"(b[1]));
}

__device__ __forceinline__ uint32_t packh2(float x, float y) {
    __half2 h = __floats2half2_rn(x, y);
    return *reinterpret_cast<uint32_t*>(&h);
}

// fp16 tile layout: 128 rows x 32 k-halves (64B data) at 80B pitch.
// 80B = 20 banks -> 8 consecutive rows hit 8 distinct banks (ldmatrix-safe),
// and the (n=lane>>2, k=lane&3) B LDS.32 pattern covers all 32 banks.
#define TP  80
#define TSZ (128 * TP)
#define XA0 0
#define XA1 TSZ
#define XB0 (2 * TSZ)
#define XB1 (3 * TSZ)
#define X_DYN (4 * TSZ + 128)

// ---------------------------------------------------------------------------
// Conversion / transpose prolog kernels
// ---------------------------------------------------------------------------
__global__ __launch_bounds__(256) void k_cvtz(const float* __restrict__ z1,
                                              const float* __restrict__ z2) {
    size_t t = (size_t)blockIdx.x * 256 + threadIdx.x;  // 1M float4-groups
    int v = (int)(t >> 19);
    size_t i = t & 524287;
    float4 a = *((const float4*)(v ? z2 : z1) + i);
    *(uint2*)((char*)g_z16[v] + i * 8) = make_uint2(packh2(a.x, a.y), packh2(a.z, a.w));
}

// dst[c][r] = (half)src[r][c]; src is [rows][cols]
__global__ __launch_bounds__(256) void k_transcvt(const float* __restrict__ src,
                                                  __half* __restrict__ dst,
                                                  int rows, int cols) {
    __shared__ float t[32][33];
    int bx = blockIdx.x * 32;  // src row
    int by = blockIdx.y * 32;  // src col
    int tx = threadIdx.x & 31, ty = threadIdx.x >> 5;
#pragma unroll
    for (int i = 0; i < 4; i++)
        t[ty + 8 * i][tx] = src[(size_t)(bx + ty + 8 * i) * cols + by + tx];
    __syncthreads();
#pragma unroll
    for (int i = 0; i < 4; i++)
        dst[(size_t)(by + ty + 8 * i) * rows + bx + tx] = __float2half_rn(t[tx][ty + 8 * i]);
}

// ---------------------------------------------------------------------------
// Row inverse L2 norms for p1, p2, q1, q2
// ---------------------------------------------------------------------------
__global__ __launch_bounds__(256) void k_norms(const float* __restrict__ p1,
                                               const float* __restrict__ p2) {
    int mat = blockIdx.y;
    const float* X = (mat == 0) ? p1 : (mat == 1) ? p2 : g_Q[mat - 2];
    int row = blockIdx.x * 8 + (threadIdx.x >> 5);
    int lane = threadIdx.x & 31;
    const float* xr = X + (size_t)row * NE;
    float s = 0.f;
#pragma unroll
    for (int j = 0; j < NE; j += 32) {
        float x = xr[j + lane];
        s = fmaf(x, x, s);
    }
#pragma unroll
    for (int o = 16; o; o >>= 1) s += __shfl_xor_sync(0xffffffffu, s, o);
    if (lane == 0) g_inorm[mat][row] = 1.f / fmaxf(sqrtf(s), 1e-12f);
}

// transpose + normalize + cvt fp16: p1->PT[0], p2->PT[1], q1->VT[1], q2->VT[0]
__global__ __launch_bounds__(256) void k_transnorm16(const float* __restrict__ p1,
                                                     const float* __restrict__ p2) {
    __shared__ float t[32][33];
    int z = blockIdx.z;
    const float* X = (z == 0) ? p1 : (z == 1) ? p2 : g_Q[z - 2];
    const float* nrm = g_inorm[z];
    __half* O = (z == 0) ? g_PT16[0] : (z == 1) ? g_PT16[1]
              : (z == 2) ? g_VT16[1] : g_VT16[0];
    int bx = blockIdx.x * 32;  // over B
    int by = blockIdx.y * 32;  // over E
    int tx = threadIdx.x & 31, ty = threadIdx.x >> 5;
#pragma unroll
    for (int i = 0; i < 4; i++) {
        int r = bx + ty + 8 * i;
        t[ty + 8 * i][tx] = X[(size_t)r * NE + by + tx] * nrm[r];
    }
    __syncthreads();
#pragma unroll
    for (int i = 0; i < 4; i++)
        O[(size_t)(by + ty + 8 * i) * NB + bx + tx] = __float2half_rn(t[tx][ty + 8 * i]);
}

// ---------------------------------------------------------------------------
// GEMM1: H[v] = z_v @ W1  (fp16 mma m16n8k16), CTA 128x128, warp 64x32.
// Fused BN partial column sums in epilogue. grid (32, 64, 2), 256 threads
// ---------------------------------------------------------------------------
__global__ __launch_bounds__(256) void k_gemm1() {
    extern __shared__ char smraw[];
    uint32_t sb0 = smem_u32(smraw);
    uint32_t pad = (128u - (sb0 & 127u)) & 127u;
    char* sm = smraw + pad;
    uint32_t sb = sb0 + pad;

    const int v = blockIdx.z;
    const __half* __restrict__ A = g_z16[v];
    const int m0 = blockIdx.y * 128, n0 = blockIdx.x * 128;
    const int tid = threadIdx.x;
    const int lane = tid & 31, wid = tid >> 5;
    const int gid = lane >> 2, tig = lane & 3;
    const int wm = (wid >> 2) * 64, wn = (wid & 3) * 32;
    const int l15 = lane & 15, l16 = lane >> 4;

    float d[4][4][4] = {};

    auto loadA = [&](int c, int buf) {
        uint32_t base = sb + (buf ? XA1 : XA0);
        const __half* Ab = A + (size_t)m0 * NE + c * 32;
#pragma unroll
        for (int i = 0; i < 2; i++) {
            int e = i * 256 + tid;
            int row = e >> 2, p = e & 3;
            cp16(base + row * TP + p * 16, Ab + (size_t)row * NE + p * 8);
        }
    };
    auto loadB = [&](int c, int buf) {
        uint32_t base = sb + (buf ? XB1 : XB0);
        const __half* Bb = g_W1T16 + (size_t)n0 * NE + c * 32;
#pragma unroll
        for (int i = 0; i < 2; i++) {
            int e = i * 256 + tid;
            int row = e >> 2, p = e & 3;
            cp16(base + row * TP + p * 16, Bb + (size_t)row * NE + p * 8);
        }
    };

    loadA(0, 0); loadB(0, 0); CP_COMMIT(); CP_WAIT0();
    __syncthreads();

    const int NC = NE / 32;  // 8
    for (int c = 0; c < NC; c++) {
        int cur = c & 1;
        if (c + 1 < NC) { loadA(c + 1, cur ^ 1); loadB(c + 1, cur ^ 1); CP_COMMIT(); }
        uint32_t ab = sb + (cur ? XA1 : XA0);
        char* bp = sm + (cur ? XB1 : XB0);
#pragma unroll
        for (int ks = 0; ks < 2; ks++) {
            uint32_t afr[4][4];
#pragma unroll
            for (int mt = 0; mt < 4; mt++)
                ldsm4(afr[mt], ab + (uint32_t)((wm + mt * 16 + l15) * TP + ks * 32 + l16 * 16));
            uint32_t bfr[4][2];
#pragma unroll
            for (int nt = 0; nt < 4; nt++) {
                int bo = (wn + nt * 8 + gid) * TP + ks * 32 + tig * 4;
                bfr[nt][0] = *(const uint32_t*)(bp + bo);
                bfr[nt][1] = *(const uint32_t*)(bp + bo + 16);
            }
#pragma unroll
            for (int mt = 0; mt < 4; mt++)
#pragma unroll
                for (int nt = 0; nt < 4; nt++)
                    mma16(d[mt][nt], afr[mt], bfr[nt]);
        }
        if (c + 1 < NC) CP_WAIT0();
        __syncthreads();
    }

    // epilogue: store H fp32
    float* C = g_H[v];
#pragma unroll
    for (int mt = 0; mt < 4; mt++) {
        int r0 = m0 + wm + mt * 16 + gid;
#pragma unroll
        for (int nt = 0; nt < 4; nt++) {
            int cc = n0 + wn + nt * 8 + 2 * tig;
            *(float2*)&C[(size_t)r0 * NH + cc] = make_float2(d[mt][nt][0], d[mt][nt][1]);
            *(float2*)&C[(size_t)(r0 + 8) * NH + cc] = make_float2(d[mt][nt][2], d[mt][nt][3]);
        }
    }

    // fused BN partial sums over this block's 128 rows
    float s[4][2], ss[4][2];
#pragma unroll
    for (int nt = 0; nt < 4; nt++)
#pragma unroll
        for (int j = 0; j < 2; j++) {
            float a = 0.f, b = 0.f;
#pragma unroll
            for (int mt = 0; mt < 4; mt++) {
                float x = d[mt][nt][j], y = d[mt][nt][2 + j];
                a += x + y;
                b = fmaf(x, x, fmaf(y, y, b));
            }
            s[nt][j] = a; ss[nt][j] = b;
        }
#pragma unroll
    for (int o = 4; o <= 16; o <<= 1) {
#pragma unroll
        for (int nt = 0; nt < 4; nt++)
#pragma unroll
            for (int j = 0; j < 2; j++) {
                s[nt][j] += __shfl_xor_sync(0xffffffffu, s[nt][j], o);
                ss[nt][j] += __shfl_xor_sync(0xffffffffu, ss[nt][j], o);
            }
    }
    __syncthreads();
    float* red = (float*)sm;  // [2 stats][2 wrow][128 col]
    int wrow = wid >> 2;
    if (gid == 0) {
#pragma unroll
        for (int nt = 0; nt < 4; nt++)
#pragma unroll
            for (int j = 0; j < 2; j++) {
                int col = wn + nt * 8 + 2 * tig + j;
                red[wrow * 128 + col] = s[nt][j];
                red[256 + wrow * 128 + col] = ss[nt][j];
            }
    }
    __syncthreads();
    {
        int col = tid & 127, stat = tid >> 7;
        float val = red[stat * 256 + col] + red[stat * 256 + 128 + col];
        if (stat == 0) g_psum[v][blockIdx.y][n0 + col] = val;
        else           g_psumsq[v][blockIdx.y][n0 + col] = val;
    }
}

// Finalize BN: scale/shift per (view, hidden unit). grid 32 x 256
__global__ void k_bnfin(const float* __restrict__ gamma,
                        const float* __restrict__ beta) {
    int i = blockIdx.x * 256 + threadIdx.x;
    int v = i >> 12;
    int h = i & (NH - 1);
    float s = 0.f, s2 = 0.f;
#pragma unroll
    for (int b = 0; b < 64; b++) { s += g_psum[v][b][h]; s2 += g_psumsq[v][b][h]; }
    float mu = s * (1.f / NB);
    float var = s2 * (1.f / NB) - mu * mu;
    float scl = rsqrtf(var + BN_EPS) * gamma[h];
    g_scale[v][h] = scl;
    g_shift[v][h] = fmaf(-mu, scl, beta[h]);
}

// ---------------------------------------------------------------------------
// GEMM2: Q[v] = relu(bn(H[v])) @ W2 + b2. A built fp32->fp16 on LDG->STS path.
// grid (2, 64, 2), 256 threads
// ---------------------------------------------------------------------------
__global__ __launch_bounds__(256) void k_gemm2(const float* __restrict__ b2) {
    extern __shared__ char smraw[];
    uint32_t sb0 = smem_u32(smraw);
    uint32_t pad = (128u - (sb0 & 127u)) & 127u;
    char* sm = smraw + pad;
    uint32_t sb = sb0 + pad;

    const int v = blockIdx.z;
    const float* __restrict__ A = g_H[v];
    const float* __restrict__ sc = g_scale[v];
    const float* __restrict__ sh = g_shift[v];
    const int m0 = blockIdx.y * 128, n0 = blockIdx.x * 128;
    const int tid = threadIdx.x;
    const int lane = tid & 31, wid = tid >> 5;
    const int gid = lane >> 2, tig = lane & 3;
    const int wm = (wid >> 2) * 64, wn = (wid & 3) * 32;
    const int l15 = lane & 15, l16 = lane >> 4;

    float d[4][4][4] = {};
    float4 areg[4];

    auto ldgA = [&](int c) {
        const float* Ab = A + (size_t)m0 * NH + c * 32;
#pragma unroll
        for (int i = 0; i < 4; i++) {
            int e = i * 256 + tid;
            int row = e >> 3, kc = (e & 7) * 4;
            areg[i] = *(const float4*)(Ab + (size_t)row * NH + kc);
        }
    };
    auto stsA = [&](int c, int buf) {
        char* base = sm + (buf ? XA1 : XA0);
#pragma unroll
        for (int i = 0; i < 4; i++) {
            int e = i * 256 + tid;
            int row = e >> 3, kc = (e & 7) * 4;
            float4 s4 = *(const float4*)(sc + c * 32 + kc);
            float4 t4 = *(const float4*)(sh + c * 32 + kc);
            float ax = fmaxf(fmaf(areg[i].x, s4.x, t4.x), 0.f);
            float ay = fmaxf(fmaf(areg[i].y, s4.y, t4.y), 0.f);
            float az = fmaxf(fmaf(areg[i].z, s4.z, t4.z), 0.f);
            float aw = fmaxf(fmaf(areg[i].w, s4.w, t4.w), 0.f);
            *(uint2*)(base + row * TP + (e & 7) * 8) =
                make_uint2(packh2(ax, ay), packh2(az, aw));
        }
    };
    auto loadB = [&](int c, int buf) {
        uint32_t base = sb + (buf ? XB1 : XB0);
        const __half* Bb = g_W2T16 + (size_t)n0 * NH + c * 32;
#pragma unroll
        for (int i = 0; i < 2; i++) {
            int e = i * 256 + tid;
            int row = e >> 2, p = e & 3;
            cp16(base + row * TP + p * 16, Bb + (size_t)row * NH + p * 8);
        }
    };

    ldgA(0); loadB(0, 0); CP_COMMIT();
    stsA(0, 0);
    CP_WAIT0();
    __syncthreads();

    const int NC = NH / 32;  // 128
    for (int c = 0; c < NC; c++) {
        int cur = c & 1;
        if (c + 1 < NC) { ldgA(c + 1); loadB(c + 1, cur ^ 1); CP_COMMIT(); }
        uint32_t ab = sb + (cur ? XA1 : XA0);
        char* bp = sm + (cur ? XB1 : XB0);
#pragma unroll
        for (int ks = 0; ks < 2; ks++) {
            uint32_t afr[4][4];
#pragma unroll
            for (int mt = 0; mt < 4; mt++)
                ldsm4(afr[mt], ab + (uint32_t)((wm + mt * 16 + l15) * TP + ks * 32 + l16 * 16));
            uint32_t bfr[4][2];
#pragma unroll
            for (int nt = 0; nt < 4; nt++) {
                int bo = (wn + nt * 8 + gid) * TP + ks * 32 + tig * 4;
                bfr[nt][0] = *(const uint32_t*)(bp + bo);
                bfr[nt][1] = *(const uint32_t*)(bp + bo + 16);
            }
#pragma unroll
            for (int mt = 0; mt < 4; mt++)
#pragma unroll
                for (int nt = 0; nt < 4; nt++)
                    mma16(d[mt][nt], afr[mt], bfr[nt]);
        }
        if (c + 1 < NC) { stsA(c + 1, cur ^ 1); CP_WAIT0(); }
        __syncthreads();
    }

    float* C = g_Q[v];
#pragma unroll
    for (int mt = 0; mt < 4; mt++) {
        int r0 = m0 + wm + mt * 16 + gid;
#pragma unroll
        for (int nt = 0; nt < 4; nt++) {
            int cc = n0 + wn + nt * 8 + 2 * tig;
            float2 bias = *(const float2*)(b2 + cc);
            *(float2*)&C[(size_t)r0 * NE + cc] =
                make_float2(d[mt][nt][0] + bias.x, d[mt][nt][1] + bias.y);
            *(float2*)&C[(size_t)(r0 + 8) * NE + cc] =
                make_float2(d[mt][nt][2] + bias.x, d[mt][nt][3] + bias.y);
        }
    }
}

// ---------------------------------------------------------------------------
// M-GEMM (split-K): Mp[mec][s] = VT16[mec][i,:slice] . PT16[mec][j,:slice]^T
// grid (2 j, 2 i, 32 = mec*16+split), K per split = 512
// ---------------------------------------------------------------------------
__global__ __launch_bounds__(256) void k_gemmM() {
    extern __shared__ char smraw[];
    uint32_t sb0 = smem_u32(smraw);
    uint32_t pad = (128u - (sb0 & 127u)) & 127u;
    char* sm = smraw + pad;
    uint32_t sb = sb0 + pad;

    const int mec = blockIdx.z >> 4;
    const int split = blockIdx.z & 15;
    const __half* __restrict__ A = g_VT16[mec];
    const __half* __restrict__ B = g_PT16[mec];
    const int i0 = blockIdx.y * 128, j0 = blockIdx.x * 128;
    const int kbase = split * 512;
    const int tid = threadIdx.x;
    const int lane = tid & 31, wid = tid >> 5;
    const int gid = lane >> 2, tig = lane & 3;
    const int wm = (wid >> 2) * 64, wn = (wid & 3) * 32;
    const int l15 = lane & 15, l16 = lane >> 4;

    float d[4][4][4] = {};

    auto loadA = [&](int c, int buf) {
        uint32_t base = sb + (buf ? XA1 : XA0);
        const __half* Ab = A + (size_t)i0 * NB + kbase + c * 32;
#pragma unroll
        for (int i = 0; i < 2; i++) {
            int e = i * 256 + tid;
            int row = e >> 2, p = e & 3;
            cp16(base + row * TP + p * 16, Ab + (size_t)row * NB + p * 8);
        }
    };
    auto loadB = [&](int c, int buf) {
        uint32_t base = sb + (buf ? XB1 : XB0);
        const __half* Bb = B + (size_t)j0 * NB + kbase + c * 32;
#pragma unroll
        for (int i = 0; i < 2; i++) {
            int e = i * 256 + tid;
            int row = e >> 2, p = e & 3;
            cp16(base + row * TP + p * 16, Bb + (size_t)row * NB + p * 8);
        }
    };

    loadA(0, 0); loadB(0, 0); CP_COMMIT(); CP_WAIT0();
    __syncthreads();

    const int NC = 16;  // 512 / 32
    for (int c = 0; c < NC; c++) {
        int cur = c & 1;
        if (c + 1 < NC) { loadA(c + 1, cur ^ 1); loadB(c + 1, cur ^ 1); CP_COMMIT(); }
        uint32_t ab = sb + (cur ? XA1 : XA0);
        char* bp = sm + (cur ? XB1 : XB0);
#pragma unroll
        for (int ks = 0; ks < 2; ks++) {
            uint32_t afr[4][4];
#pragma unroll
            for (int mt = 0; mt < 4; mt++)
                ldsm4(afr[mt], ab + (uint32_t)((wm + mt * 16 + l15) * TP + ks * 32 + l16 * 16));
            uint32_t bfr[4][2];
#pragma unroll
            for (int nt = 0; nt < 4; nt++) {
                int bo = (wn + nt * 8 + gid) * TP + ks * 32 + tig * 4;
                bfr[nt][0] = *(const uint32_t*)(bp + bo);
                bfr[nt][1] = *(const uint32_t*)(bp + bo + 16);
            }
#pragma unroll
            for (int mt = 0; mt < 4; mt++)
#pragma unroll
                for (int nt = 0; nt < 4; nt++)
                    mma16(d[mt][nt], afr[mt], bfr[nt]);
        }
        if (c + 1 < NC) CP_WAIT0();
        __syncthreads();
    }

    float* O = g_Mp[mec][split];
#pragma unroll
    for (int mt = 0; mt < 4; mt++) {
        int r0 = i0 + wm + mt * 16 + gid;
#pragma unroll
        for (int nt = 0; nt < 4; nt++) {
            int cc = j0 + wn + nt * 8 + 2 * tig;
            *(float2*)&O[(size_t)r0 * NE + cc] = make_float2(d[mt][nt][0], d[mt][nt][1]);
            *(float2*)&O[(size_t)(r0 + 8) * NE + cc] = make_float2(d[mt][nt][2], d[mt][nt][3]);
        }
    }
}

// Reduce split-K partials and apply 1/lamda_inv. grid (256, 2)
__global__ void k_Mred(const float* __restrict__ plam) {
    int m = blockIdx.y;
    int i = blockIdx.x * 256 + threadIdx.x;
    float inv = 1.f / *plam;
    float s = 0.f;
#pragma unroll
    for (int ks = 0; ks < 16; ks++) s += g_Mp[m][ks][i];
    g_M[m][i] = s * inv;
}

// ---------------------------------------------------------------------------
// M2 = M @ M (256^3), traces, final scalar
// ---------------------------------------------------------------------------
__global__ __launch_bounds__(256) void k_M2() {
    const int m = blockIdx.z;
    const float* M = g_M[m];
    float* O = g_M2[m];
    __shared__ float As[16][64];
    __shared__ float Bs[16][64];
    const int tid = threadIdx.x;
    const int tx = tid & 15, ty = tid >> 4;
    const int i0 = blockIdx.y * 64, j0 = blockIdx.x * 64;
    const int ai = tid >> 2, ak = (tid & 3) * 4;
    const int bk = tid >> 4, bj = (tid & 15) * 4;
    float acc[4][4] = {};
    for (int kb = 0; kb < NE; kb += 16) {
        float4 av = *(const float4*)(M + (i0 + ai) * NE + kb + ak);
        float4 bv = *(const float4*)(M + (kb + bk) * NE + j0 + bj);
        __syncthreads();
        As[ak + 0][ai] = av.x; As[ak + 1][ai] = av.y;
        As[ak + 2][ai] = av.z; As[ak + 3][ai] = av.w;
        *(float4*)&Bs[bk][bj] = bv;
        __syncthreads();
#pragma unroll
        for (int k = 0; k < 16; k++) {
            float a[4], bb[4];
            *(float4*)a = *(const float4*)&As[k][ty * 4];
            *(float4*)bb = *(const float4*)&Bs[k][tx * 4];
#pragma unroll
            for (int ii = 0; ii < 4; ii++)
#pragma unroll
                for (int jj = 0; jj < 4; jj++)
                    acc[ii][jj] = fmaf(a[ii], bb[jj], acc[ii][jj]);
        }
    }
#pragma unroll
    for (int ii = 0; ii < 4; ii++)
#pragma unroll
        for (int jj = 0; jj < 4; jj++)
            O[(i0 + ty * 4 + ii) * NE + j0 + tx * 4 + jj] = acc[ii][jj];
}

__global__ __launch_bounds__(256) void k_traces() {
    const int m = blockIdx.y;
    const float* M = g_M[m];
    const float* M2 = g_M2[m];
    const int tid = threadIdx.x;
    const int idx0 = blockIdx.x * 2048;
    float t1 = 0.f, t2 = 0.f, t3 = 0.f, t4 = 0.f;
    for (int idx = idx0 + tid; idx < idx0 + 2048; idx += 256) {
        int i = idx >> 8, j = idx & 255;
        float mij = M[idx], mji = M[j * NE + i];
        float m2ij = M2[idx], m2ji = M2[j * NE + i];
        if (i == j) t1 += mij;
        t2 = fmaf(mij, mji, t2);
        t3 = fmaf(m2ij, mji, t3);
        t4 = fmaf(m2ij, m2ji, t4);
    }
    __shared__ float red[4][256];
    red[0][tid] = t1; red[1][tid] = t2; red[2][tid] = t3; red[3][tid] = t4;
    __syncthreads();
    for (int s = 128; s > 0; s >>= 1) {
        if (tid < s) {
            red[0][tid] += red[0][tid + s];
            red[1][tid] += red[1][tid + s];
            red[2][tid] += red[2][tid + s];
            red[3][tid] += red[3][tid + s];
        }
        __syncthreads();
    }
    if (tid < 4) g_tp[m][blockIdx.x][tid] = red[tid][0];
}

__global__ void k_final(const float* __restrict__ plam, float* __restrict__ out) {
    float t[2][4];
    for (int m = 0; m < 2; m++)
        for (int c = 0; c < 4; c++) {
            float s = 0.f;
            for (int b = 0; b < 32; b++) s += g_tp[m][b][c];
            t[m][c] = s;
        }
    float s0 = t[0][0] - 0.5f * t[0][1] + (1.f / 3.f) * t[0][2] - 0.25f * t[0][3];
    float s1 = t[1][0] - 0.5f * t[1][1] + (1.f / 3.f) * t[1][2] - 0.25f * t[1][3];
    float loss = (s0 + s1) * 0.5f / (float)NB;
    out[0] = -loss * (*plam);
}

// ---------------------------------------------------------------------------
// Launch
// ---------------------------------------------------------------------------
extern "C" void kernel_launch(void* const* d_in, const int* in_sizes, int n_in,
                              void* d_out, int out_size) {
    const float* z1    = (const float*)d_in[0];
    const float* z2    = (const float*)d_in[1];
    const float* p1    = (const float*)d_in[2];
    const float* p2    = (const float*)d_in[3];
    const float* W1    = (const float*)d_in[4];
    const float* gamma = (const float*)d_in[5];
    const float* beta  = (const float*)d_in[6];
    const float* W2    = (const float*)d_in[7];
    const float* b2    = (const float*)d_in[8];
    const float* plam  = (const float*)d_in[9];
    float* out = (float*)d_out;

    __half* w1t16; cudaGetSymbolAddress((void**)&w1t16, g_W1T16);
    __half* w2t16; cudaGetSymbolAddress((void**)&w2t16, g_W2T16);

    cudaFuncSetAttribute(k_gemm1, cudaFuncAttributeMaxDynamicSharedMemorySize, X_DYN);
    cudaFuncSetAttribute(k_gemm2, cudaFuncAttributeMaxDynamicSharedMemorySize, X_DYN);
    cudaFuncSetAttribute(k_gemmM, cudaFuncAttributeMaxDynamicSharedMemorySize, X_DYN);

    // 0) prolog: z -> fp16; W1^T, W2^T -> fp16 (n-major for cp.async B tiles)
    k_cvtz<<<4096, 256>>>(z1, z2);
    k_transcvt<<<dim3(NE / 32, NH / 32), 256>>>(W1, w1t16, NE, NH);
    k_transcvt<<<dim3(NH / 32, NE / 32), 256>>>(W2, w2t16, NH, NE);
    // 1) H = z @ W1 (fp16 mma) + fused BN partial stats; finalize BN
    k_gemm1<<<dim3(NH / 128, NB / 128, 2), 256, X_DYN>>>();
    k_bnfin<<<(2 * NH) / 256, 256>>>(gamma, beta);
    // 2) Q = relu(bn(H)) @ W2 + b2
    k_gemm2<<<dim3(NE / 128, NB / 128, 2), 256, X_DYN>>>(b2);
    // 3) norms; transpose+normalize p's and q's to fp16
    k_norms<<<dim3(NB / 8, 4), 256>>>(p1, p2);
    k_transnorm16<<<dim3(NB / 32, NE / 32, 4), 256>>>(p1, p2);
    // 4) M via split-K fp16 GEMM + deterministic reduce (applies 1/lamda_inv)
    k_gemmM<<<dim3(NE / 128, NE / 128, 32), 256, X_DYN>>>();
    k_Mred<<<dim3((NE * NE) / 256, 2), 256>>>(plam);
    // 5) M2, traces, final
    k_M2<<<dim3(NE / 64, NE / 64, 2), 256>>>();
    k_traces<<<dim3(32, 2), 256>>>();
    k_final<<<1, 1>>>(plam, out);
}

// round 15
// speedup vs baseline: 1.4827x; 1.0728x over previous
#include <cuda_runtime.h>
#include <cuda_fp16.h>
#include <math.h>
#include <stdint.h>

// Problem dims (fixed by the reference)
#define NB 8192   // batch
#define NE 256    // embedding
#define NH 4096   // hidden
#define BN_EPS 1e-5f

// ---------------------------------------------------------------------------
// Scratch (device globals: allocation-free)
// ---------------------------------------------------------------------------
__device__ __half g_H16[2][NB * NH];       // 128 MB: pre-BN hidden per view (fp16)
__device__ float g_Q[2][NB * NE];          // 16 MB: predictor outputs
__device__ float g_psum[2][64][NH];        // per-128-rowblock partial col sums
__device__ float g_psumsq[2][64][NH];
__device__ float g_scale[2][NH];
__device__ float g_shift[2][NH];
__device__ float g_inorm[4][NB];           // inv row norms: p1,p2,q1,q2
__device__ __half g_z16[2][NB * NE];       // fp16 z views
__device__ __half g_W1T16[NH * NE];        // W1^T fp16 [H][E]
__device__ __half g_W2T16[NE * NH];        // W2^T fp16 [E][H]
__device__ __half g_VT16[2][NE * NB];      // VT16[0]=q2n^T, VT16[1]=q1n^T
__device__ __half g_PT16[2][NE * NB];      // PT16[0]=p1n^T, PT16[1]=p2n^T
__device__ float g_Mp[2][16][NE * NE];     // split-K partials of M
__device__ float g_M[2][NE * NE];
__device__ float g_M2[2][NE * NE];
__device__ float g_tp[2][32][4];

// ---------------------------------------------------------------------------
// Baseline-PTX helpers (compute_103-safe: cp.async / ldmatrix / mma.sync)
// ---------------------------------------------------------------------------
__device__ __forceinline__ uint32_t smem_u32(const void* p) {
    uint32_t a;
    asm("{ .reg .u64 t; cvta.to.shared.u64 t, %1; cvt.u32.u64 %0, t; }"
        : "=r"(a) : "l"(p));
    return a;
}

__device__ __forceinline__ void cp16(uint32_t dst, const void* src) {
    asm volatile("cp.async.cg.shared.global [%0], [%1], 16;" :: "r"(dst), "l"(src));
}
#define CP_COMMIT() asm volatile("cp.async.commit_group;" ::: "memory")
#define CP_WAIT0()  asm volatile("cp.async.wait_group 0;" ::: "memory")
#define CP_WAIT1()  asm volatile("cp.async.wait_group 1;" ::: "memory")

__device__ __forceinline__ void ldsm4(uint32_t* r, uint32_t a) {
    asm volatile("ldmatrix.sync.aligned.m8n8.x4.shared.b16 {%0,%1,%2,%3}, [%4];"
                 : "=r"(r[0]), "=r"(r[1]), "=r"(r[2]), "=r"(r[3]) : "r"(a));
}

// fp16 mma with fp32 accumulate (baseline PTX, sm_80-era)
__device__ __forceinline__ void mma16(float* d, const uint32_t* a, const uint32_t* b) {
    asm volatile(
        "mma.sync.aligned.m16n8k16.row.col.f32.f16.f16.f32 "
        "{%0,%1,%2,%3}, {%4,%5,%6,%7}, {%8,%9}, {%0,%1,%2,%3};"
        : "+f"(d[0]), "+f"(d[1]), "+f"(d[2]), "+f"(d[3])
        : "r"(a[0]), "r"(a[1]), "r"(a[2]), "r"(a[3]), "r"(b[0]), "r"(b[1]));
}

__device__ __forceinline__ uint32_t packh2(float x, float y) {
    __half2 h = __floats2half2_rn(x, y);
    return *reinterpret_cast<uint32_t*>(&h);
}

// fp16 tile layout: 128 rows x 32 k-halves (64B data) at 80B pitch.
#define TP  80
#define TSZ (128 * TP)
// 3-stage layout (gemm1, gemmM): A at st*TSZ, B at (3+st)*TSZ
#define X3_DYN (6 * TSZ + 128)
// 2-stage layout (gemm2): A buffers 0/1, B buffers 2/3
#define XA0 0
#define XA1 TSZ
#define XB0 (2 * TSZ)
#define XB1 (3 * TSZ)
#define X2_DYN (4 * TSZ + 128)

// ---------------------------------------------------------------------------
// Conversion / transpose prolog kernels
// ---------------------------------------------------------------------------
__global__ __launch_bounds__(256) void k_cvtz(const float* __restrict__ z1,
                                              const float* __restrict__ z2) {
    size_t t = (size_t)blockIdx.x * 256 + threadIdx.x;  // 1M float4-groups
    int v = (int)(t >> 19);
    size_t i = t & 524287;
    float4 a = *((const float4*)(v ? z2 : z1) + i);
    *(uint2*)((char*)g_z16[v] + i * 8) = make_uint2(packh2(a.x, a.y), packh2(a.z, a.w));
}

// dst[c][r] = (half)src[r][c]; src is [rows][cols]
__global__ __launch_bounds__(256) void k_transcvt(const float* __restrict__ src,
                                                  __half* __restrict__ dst,
                                                  int rows, int cols) {
    __shared__ float t[32][33];
    int bx = blockIdx.x * 32;  // src row
    int by = blockIdx.y * 32;  // src col
    int tx = threadIdx.x & 31, ty = threadIdx.x >> 5;
#pragma unroll
    for (int i = 0; i < 4; i++)
        t[ty + 8 * i][tx] = src[(size_t)(bx + ty + 8 * i) * cols + by + tx];
    __syncthreads();
#pragma unroll
    for (int i = 0; i < 4; i++)
        dst[(size_t)(by + ty + 8 * i) * rows + bx + tx] = __float2half_rn(t[tx][ty + 8 * i]);
}

// ---------------------------------------------------------------------------
// Row inverse L2 norms for p1, p2, q1, q2
// ---------------------------------------------------------------------------
__global__ __launch_bounds__(256) void k_norms(const float* __restrict__ p1,
                                               const float* __restrict__ p2) {
    int mat = blockIdx.y;
    const float* X = (mat == 0) ? p1 : (mat == 1) ? p2 : g_Q[mat - 2];
    int row = blockIdx.x * 8 + (threadIdx.x >> 5);
    int lane = threadIdx.x & 31;
    const float* xr = X + (size_t)row * NE;
    float s = 0.f;
#pragma unroll
    for (int j = 0; j < NE; j += 32) {
        float x = xr[j + lane];
        s = fmaf(x, x, s);
    }
#pragma unroll
    for (int o = 16; o; o >>= 1) s += __shfl_xor_sync(0xffffffffu, s, o);
    if (lane == 0) g_inorm[mat][row] = 1.f / fmaxf(sqrtf(s), 1e-12f);
}

// transpose + normalize + cvt fp16: p1->PT[0], p2->PT[1], q1->VT[1], q2->VT[0]
__global__ __launch_bounds__(256) void k_transnorm16(const float* __restrict__ p1,
                                                     const float* __restrict__ p2) {
    __shared__ float t[32][33];
    int z = blockIdx.z;
    const float* X = (z == 0) ? p1 : (z == 1) ? p2 : g_Q[z - 2];
    const float* nrm = g_inorm[z];
    __half* O = (z == 0) ? g_PT16[0] : (z == 1) ? g_PT16[1]
              : (z == 2) ? g_VT16[1] : g_VT16[0];
    int bx = blockIdx.x * 32;  // over B
    int by = blockIdx.y * 32;  // over E
    int tx = threadIdx.x & 31, ty = threadIdx.x >> 5;
#pragma unroll
    for (int i = 0; i < 4; i++) {
        int r = bx + ty + 8 * i;
        t[ty + 8 * i][tx] = X[(size_t)r * NE + by + tx] * nrm[r];
    }
    __syncthreads();
#pragma unroll
    for (int i = 0; i < 4; i++)
        O[(size_t)(by + ty + 8 * i) * NB + bx + tx] = __float2half_rn(t[tx][ty + 8 * i]);
}

// ---------------------------------------------------------------------------
// GEMM1: H[v] = z_v @ W1  (fp16 mma m16n8k16), CTA 128x128, warp 64x32.
// 3-stage cp.async pipeline. Fused BN partial sums + fp16 H store in epilogue.
// grid (32, 64, 2), 256 threads
// ---------------------------------------------------------------------------
__global__ __launch_bounds__(256) void k_gemm1() {
    extern __shared__ char smraw[];
    uint32_t sb0 = smem_u32(smraw);
    uint32_t pad = (128u - (sb0 & 127u)) & 127u;
    char* sm = smraw + pad;
    uint32_t sb = sb0 + pad;

    const int v = blockIdx.z;
    const __half* __restrict__ A = g_z16[v];
    const int m0 = blockIdx.y * 128, n0 = blockIdx.x * 128;
    const int tid = threadIdx.x;
    const int lane = tid & 31, wid = tid >> 5;
    const int gid = lane >> 2, tig = lane & 3;
    const int wm = (wid >> 2) * 64, wn = (wid & 3) * 32;
    const int l15 = lane & 15, l16 = lane >> 4;

    float d[4][4][4] = {};

    auto loadA = [&](int c, int st) {
        uint32_t base = sb + st * TSZ;
        const __half* Ab = A + (size_t)m0 * NE + c * 32;
#pragma unroll
        for (int i = 0; i < 2; i++) {
            int e = i * 256 + tid;
            int row = e >> 2, p = e & 3;
            cp16(base + row * TP + p * 16, Ab + (size_t)row * NE + p * 8);
        }
    };
    auto loadB = [&](int c, int st) {
        uint32_t base = sb + (3 + st) * TSZ;
        const __half* Bb = g_W1T16 + (size_t)n0 * NE + c * 32;
#pragma unroll
        for (int i = 0; i < 2; i++) {
            int e = i * 256 + tid;
            int row = e >> 2, p = e & 3;
            cp16(base + row * TP + p * 16, Bb + (size_t)row * NE + p * 8);
        }
    };

    loadA(0, 0); loadB(0, 0); CP_COMMIT();
    loadA(1, 1); loadB(1, 1); CP_COMMIT();

    const int NC = NE / 32;  // 8
    for (int c = 0; c < NC; c++) {
        int st = c % 3;
        if (c + 1 < NC) { CP_WAIT1(); } else { CP_WAIT0(); }
        __syncthreads();
        uint32_t ab = sb + st * TSZ;
        char* bp = sm + (3 + st) * TSZ;
#pragma unroll
        for (int ks = 0; ks < 2; ks++) {
            uint32_t afr[4][4];
#pragma unroll
            for (int mt = 0; mt < 4; mt++)
                ldsm4(afr[mt], ab + (uint32_t)((wm + mt * 16 + l15) * TP + ks * 32 + l16 * 16));
            uint32_t bfr[4][2];
#pragma unroll
            for (int nt = 0; nt < 4; nt++) {
                int bo = (wn + nt * 8 + gid) * TP + ks * 32 + tig * 4;
                bfr[nt][0] = *(const uint32_t*)(bp + bo);
                bfr[nt][1] = *(const uint32_t*)(bp + bo + 16);
            }
#pragma unroll
            for (int mt = 0; mt < 4; mt++)
#pragma unroll
                for (int nt = 0; nt < 4; nt++)
                    mma16(d[mt][nt], afr[mt], bfr[nt]);
        }
        if (c + 2 < NC) {
            loadA(c + 2, (c + 2) % 3);
            loadB(c + 2, (c + 2) % 3);
            CP_COMMIT();
        }
    }

    // epilogue: store H fp16
    __half* C = g_H16[v];
#pragma unroll
    for (int mt = 0; mt < 4; mt++) {
        int r0 = m0 + wm + mt * 16 + gid;
#pragma unroll
        for (int nt = 0; nt < 4; nt++) {
            int cc = n0 + wn + nt * 8 + 2 * tig;
            *(uint32_t*)&C[(size_t)r0 * NH + cc] = packh2(d[mt][nt][0], d[mt][nt][1]);
            *(uint32_t*)&C[(size_t)(r0 + 8) * NH + cc] = packh2(d[mt][nt][2], d[mt][nt][3]);
        }
    }

    // fused BN partial sums over this block's 128 rows (exact fp32 accums)
    float s[4][2], ss[4][2];
#pragma unroll
    for (int nt = 0; nt < 4; nt++)
#pragma unroll
        for (int j = 0; j < 2; j++) {
            float a = 0.f, b = 0.f;
#pragma unroll
            for (int mt = 0; mt < 4; mt++) {
                float x = d[mt][nt][j], y = d[mt][nt][2 + j];
                a += x + y;
                b = fmaf(x, x, fmaf(y, y, b));
            }
            s[nt][j] = a; ss[nt][j] = b;
        }
#pragma unroll
    for (int o = 4; o <= 16; o <<= 1) {
#pragma unroll
        for (int nt = 0; nt < 4; nt++)
#pragma unroll
            for (int j = 0; j < 2; j++) {
                s[nt][j] += __shfl_xor_sync(0xffffffffu, s[nt][j], o);
                ss[nt][j] += __shfl_xor_sync(0xffffffffu, ss[nt][j], o);
            }
    }
    __syncthreads();
    float* red = (float*)sm;  // [2 stats][2 wrow][128 col]
    int wrow = wid >> 2;
    if (gid == 0) {
#pragma unroll
        for (int nt = 0; nt < 4; nt++)
#pragma unroll
            for (int j = 0; j < 2; j++) {
                int col = wn + nt * 8 + 2 * tig + j;
                red[wrow * 128 + col] = s[nt][j];
                red[256 + wrow * 128 + col] = ss[nt][j];
            }
    }
    __syncthreads();
    {
        int col = tid & 127, stat = tid >> 7;
        float val = red[stat * 256 + col] + red[stat * 256 + 128 + col];
        if (stat == 0) g_psum[v][blockIdx.y][n0 + col] = val;
        else           g_psumsq[v][blockIdx.y][n0 + col] = val;
    }
}

// Finalize BN: scale/shift per (view, hidden unit). grid 32 x 256
__global__ void k_bnfin(const float* __restrict__ gamma,
                        const float* __restrict__ beta) {
    int i = blockIdx.x * 256 + threadIdx.x;
    int v = i >> 12;
    int h = i & (NH - 1);
    float s = 0.f, s2 = 0.f;
#pragma unroll
    for (int b = 0; b < 64; b++) { s += g_psum[v][b][h]; s2 += g_psumsq[v][b][h]; }
    float mu = s * (1.f / NB);
    float var = s2 * (1.f / NB) - mu * mu;
    float scl = rsqrtf(var + BN_EPS) * gamma[h];
    g_scale[v][h] = scl;
    g_shift[v][h] = fmaf(-mu, scl, beta[h]);
}

// ---------------------------------------------------------------------------
// GEMM2: Q[v] = relu(bn(H16[v])) @ W2 + b2. A read fp16, BN in fp32 on
// LDG->STS path, repacked fp16. grid (2, 64, 2), 256 threads
// ---------------------------------------------------------------------------
__global__ __launch_bounds__(256) void k_gemm2(const float* __restrict__ b2) {
    extern __shared__ char smraw[];
    uint32_t sb0 = smem_u32(smraw);
    uint32_t pad = (128u - (sb0 & 127u)) & 127u;
    char* sm = smraw + pad;
    uint32_t sb = sb0 + pad;

    const int v = blockIdx.z;
    const __half* __restrict__ A = g_H16[v];
    const float* __restrict__ sc = g_scale[v];
    const float* __restrict__ sh = g_shift[v];
    const int m0 = blockIdx.y * 128, n0 = blockIdx.x * 128;
    const int tid = threadIdx.x;
    const int lane = tid & 31, wid = tid >> 5;
    const int gid = lane >> 2, tig = lane & 3;
    const int wm = (wid >> 2) * 64, wn = (wid & 3) * 32;
    const int l15 = lane & 15, l16 = lane >> 4;

    float d[4][4][4] = {};
    uint4 areg[2];

    auto ldgA = [&](int c) {
        const __half* Ab = A + (size_t)m0 * NH + c * 32;
#pragma unroll
        for (int i = 0; i < 2; i++) {
            int e = i * 256 + tid;
            int row = e >> 2, p = e & 3;
            areg[i] = *(const uint4*)(Ab + (size_t)row * NH + p * 8);
        }
    };
    auto stsA = [&](int c, int buf) {
        char* base = sm + (buf ? XA1 : XA0);
#pragma unroll
        for (int i = 0; i < 2; i++) {
            int e = i * 256 + tid;
            int row = e >> 2, p = e & 3;
            int k0 = c * 32 + p * 8;
            float4 sa = *(const float4*)(sc + k0);
            float4 sb4 = *(const float4*)(sc + k0 + 4);
            float4 ta = *(const float4*)(sh + k0);
            float4 tb = *(const float4*)(sh + k0 + 4);
            const __half2* hp = (const __half2*)&areg[i];
            float2 f0 = __half22float2(hp[0]);
            float2 f1 = __half22float2(hp[1]);
            float2 f2 = __half22float2(hp[2]);
            float2 f3 = __half22float2(hp[3]);
            uint4 o;
            o.x = packh2(fmaxf(fmaf(f0.x, sa.x, ta.x), 0.f),
                         fmaxf(fmaf(f0.y, sa.y, ta.y), 0.f));
            o.y = packh2(fmaxf(fmaf(f1.x, sa.z, ta.z), 0.f),
                         fmaxf(fmaf(f1.y, sa.w, ta.w), 0.f));
            o.z = packh2(fmaxf(fmaf(f2.x, sb4.x, tb.x), 0.f),
                         fmaxf(fmaf(f2.y, sb4.y, tb.y), 0.f));
            o.w = packh2(fmaxf(fmaf(f3.x, sb4.z, tb.z), 0.f),
                         fmaxf(fmaf(f3.y, sb4.w, tb.w), 0.f));
            *(uint4*)(base + row * TP + p * 16) = o;
        }
    };
    auto loadB = [&](int c, int buf) {
        uint32_t base = sb + (buf ? XB1 : XB0);
        const __half* Bb = g_W2T16 + (size_t)n0 * NH + c * 32;
#pragma unroll
        for (int i = 0; i < 2; i++) {
            int e = i * 256 + tid;
            int row = e >> 2, p = e & 3;
            cp16(base + row * TP + p * 16, Bb + (size_t)row * NH + p * 8);
        }
    };

    ldgA(0); loadB(0, 0); CP_COMMIT();
    stsA(0, 0);
    CP_WAIT0();
    __syncthreads();

    const int NC = NH / 32;  // 128
    for (int c = 0; c < NC; c++) {
        int cur = c & 1;
        if (c + 1 < NC) { ldgA(c + 1); loadB(c + 1, cur ^ 1); CP_COMMIT(); }
        uint32_t ab = sb + (cur ? XA1 : XA0);
        char* bp = sm + (cur ? XB1 : XB0);
#pragma unroll
        for (int ks = 0; ks < 2; ks++) {
            uint32_t afr[4][4];
#pragma unroll
            for (int mt = 0; mt < 4; mt++)
                ldsm4(afr[mt], ab + (uint32_t)((wm + mt * 16 + l15) * TP + ks * 32 + l16 * 16));
            uint32_t bfr[4][2];
#pragma unroll
            for (int nt = 0; nt < 4; nt++) {
                int bo = (wn + nt * 8 + gid) * TP + ks * 32 + tig * 4;
                bfr[nt][0] = *(const uint32_t*)(bp + bo);
                bfr[nt][1] = *(const uint32_t*)(bp + bo + 16);
            }
#pragma unroll
            for (int mt = 0; mt < 4; mt++)
#pragma unroll
                for (int nt = 0; nt < 4; nt++)
                    mma16(d[mt][nt], afr[mt], bfr[nt]);
        }
        if (c + 1 < NC) { stsA(c + 1, cur ^ 1); CP_WAIT0(); }
        __syncthreads();
    }

    float* C = g_Q[v];
#pragma unroll
    for (int mt = 0; mt < 4; mt++) {
        int r0 = m0 + wm + mt * 16 + gid;
#pragma unroll
        for (int nt = 0; nt < 4; nt++) {
            int cc = n0 + wn + nt * 8 + 2 * tig;
            float2 bias = *(const float2*)(b2 + cc);
            *(float2*)&C[(size_t)r0 * NE + cc] =
                make_float2(d[mt][nt][0] + bias.x, d[mt][nt][1] + bias.y);
            *(float2*)&C[(size_t)(r0 + 8) * NE + cc] =
                make_float2(d[mt][nt][2] + bias.x, d[mt][nt][3] + bias.y);
        }
    }
}

// ---------------------------------------------------------------------------
// M-GEMM (split-K, 3-stage): Mp[mec][s] = VT16[mec] . PT16[mec]^T over slice
// grid (2 j, 2 i, 32 = mec*16+split), K per split = 512
// ---------------------------------------------------------------------------
__global__ __launch_bounds__(256) void k_gemmM() {
    extern __shared__ char smraw[];
    uint32_t sb0 = smem_u32(smraw);
    uint32_t pad = (128u - (sb0 & 127u)) & 127u;
    char* sm = smraw + pad;
    uint32_t sb = sb0 + pad;

    const int mec = blockIdx.z >> 4;
    const int split = blockIdx.z & 15;
    const __half* __restrict__ A = g_VT16[mec];
    const __half* __restrict__ B = g_PT16[mec];
    const int i0 = blockIdx.y * 128, j0 = blockIdx.x * 128;
    const int kbase = split * 512;
    const int tid = threadIdx.x;
    const int lane = tid & 31, wid = tid >> 5;
    const int gid = lane >> 2, tig = lane & 3;
    const int wm = (wid >> 2) * 64, wn = (wid & 3) * 32;
    const int l15 = lane & 15, l16 = lane >> 4;

    float d[4][4][4] = {};

    auto loadA = [&](int c, int st) {
        uint32_t base = sb + st * TSZ;
        const __half* Ab = A + (size_t)i0 * NB + kbase + c * 32;
#pragma unroll
        for (int i = 0; i < 2; i++) {
            int e = i * 256 + tid;
            int row = e >> 2, p = e & 3;
            cp16(base + row * TP + p * 16, Ab + (size_t)row * NB + p * 8);
        }
    };
    auto loadB = [&](int c, int st) {
        uint32_t base = sb + (3 + st) * TSZ;
        const __half* Bb = B + (size_t)j0 * NB + kbase + c * 32;
#pragma unroll
        for (int i = 0; i < 2; i++) {
            int e = i * 256 + tid;
            int row = e >> 2, p = e & 3;
            cp16(base + row * TP + p * 16, Bb + (size_t)row * NB + p * 8);
        }
    };

    loadA(0, 0); loadB(0, 0); CP_COMMIT();
    loadA(1, 1); loadB(1, 1); CP_COMMIT();

    const int NC = 16;  // 512 / 32
    for (int c = 0; c < NC; c++) {
        int st = c % 3;
        if (c + 1 < NC) { CP_WAIT1(); } else { CP_WAIT0(); }
        __syncthreads();
        uint32_t ab = sb + st * TSZ;
        char* bp = sm + (3 + st) * TSZ;
#pragma unroll
        for (int ks = 0; ks < 2; ks++) {
            uint32_t afr[4][4];
#pragma unroll
            for (int mt = 0; mt < 4; mt++)
                ldsm4(afr[mt], ab + (uint32_t)((wm + mt * 16 + l15) * TP + ks * 32 + l16 * 16));
            uint32_t bfr[4][2];
#pragma unroll
            for (int nt = 0; nt < 4; nt++) {
                int bo = (wn + nt * 8 + gid) * TP + ks * 32 + tig * 4;
                bfr[nt][0] = *(const uint32_t*)(bp + bo);
                bfr[nt][1] = *(const uint32_t*)(bp + bo + 16);
            }
#pragma unroll
            for (int mt = 0; mt < 4; mt++)
#pragma unroll
                for (int nt = 0; nt < 4; nt++)
                    mma16(d[mt][nt], afr[mt], bfr[nt]);
        }
        if (c + 2 < NC) {
            loadA(c + 2, (c + 2) % 3);
            loadB(c + 2, (c + 2) % 3);
            CP_COMMIT();
        }
    }

    float* O = g_Mp[mec][split];
#pragma unroll
    for (int mt = 0; mt < 4; mt++) {
        int r0 = i0 + wm + mt * 16 + gid;
#pragma unroll
        for (int nt = 0; nt < 4; nt++) {
            int cc = j0 + wn + nt * 8 + 2 * tig;
            *(float2*)&O[(size_t)r0 * NE + cc] = make_float2(d[mt][nt][0], d[mt][nt][1]);
            *(float2*)&O[(size_t)(r0 + 8) * NE + cc] = make_float2(d[mt][nt][2], d[mt][nt][3]);
        }
    }
}

// Reduce split-K partials and apply 1/lamda_inv. grid (256, 2)
__global__ void k_Mred(const float* __restrict__ plam) {
    int m = blockIdx.y;
    int i = blockIdx.x * 256 + threadIdx.x;
    float inv = 1.f / *plam;
    float s = 0.f;
#pragma unroll
    for (int ks = 0; ks < 16; ks++) s += g_Mp[m][ks][i];
    g_M[m][i] = s * inv;
}

// ---------------------------------------------------------------------------
// M2 = M @ M (256^3), traces, final scalar
// ---------------------------------------------------------------------------
__global__ __launch_bounds__(256) void k_M2() {
    const int m = blockIdx.z;
    const float* M = g_M[m];
    float* O = g_M2[m];
    __shared__ float As[16][64];
    __shared__ float Bs[16][64];
    const int tid = threadIdx.x;
    const int tx = tid & 15, ty = tid >> 4;
    const int i0 = blockIdx.y * 64, j0 = blockIdx.x * 64;
    const int ai = tid >> 2, ak = (tid & 3) * 4;
    const int bk = tid >> 4, bj = (tid & 15) * 4;
    float acc[4][4] = {};
    for (int kb = 0; kb < NE; kb += 16) {
        float4 av = *(const float4*)(M + (i0 + ai) * NE + kb + ak);
        float4 bv = *(const float4*)(M + (kb + bk) * NE + j0 + bj);
        __syncthreads();
        As[ak + 0][ai] = av.x; As[ak + 1][ai] = av.y;
        As[ak + 2][ai] = av.z; As[ak + 3][ai] = av.w;
        *(float4*)&Bs[bk][bj] = bv;
        __syncthreads();
#pragma unroll
        for (int k = 0; k < 16; k++) {
            float a[4], bb[4];
            *(float4*)a = *(const float4*)&As[k][ty * 4];
            *(float4*)bb = *(const float4*)&Bs[k][tx * 4];
#pragma unroll
            for (int ii = 0; ii < 4; ii++)
#pragma unroll
                for (int jj = 0; jj < 4; jj++)
                    acc[ii][jj] = fmaf(a[ii], bb[jj], acc[ii][jj]);
        }
    }
#pragma unroll
    for (int ii = 0; ii < 4; ii++)
#pragma unroll
        for (int jj = 0; jj < 4; jj++)
            O[(i0 + ty * 4 + ii) * NE + j0 + tx * 4 + jj] = acc[ii][jj];
}

__global__ __launch_bounds__(256) void k_traces() {
    const int m = blockIdx.y;
    const float* M = g_M[m];
    const float* M2 = g_M2[m];
    const int tid = threadIdx.x;
    const int idx0 = blockIdx.x * 2048;
    float t1 = 0.f, t2 = 0.f, t3 = 0.f, t4 = 0.f;
    for (int idx = idx0 + tid; idx < idx0 + 2048; idx += 256) {
        int i = idx >> 8, j = idx & 255;
        float mij = M[idx], mji = M[j * NE + i];
        float m2ij = M2[idx], m2ji = M2[j * NE + i];
        if (i == j) t1 += mij;
        t2 = fmaf(mij, mji, t2);
        t3 = fmaf(m2ij, mji, t3);
        t4 = fmaf(m2ij, m2ji, t4);
    }
    __shared__ float red[4][256];
    red[0][tid] = t1; red[1][tid] = t2; red[2][tid] = t3; red[3][tid] = t4;
    __syncthreads();
    for (int s = 128; s > 0; s >>= 1) {
        if (tid < s) {
            red[0][tid] += red[0][tid + s];
            red[1][tid] += red[1][tid + s];
            red[2][tid] += red[2][tid + s];
            red[3][tid] += red[3][tid + s];
        }
        __syncthreads();
    }
    if (tid < 4) g_tp[m][blockIdx.x][tid] = red[tid][0];
}

__global__ void k_final(const float* __restrict__ plam, float* __restrict__ out) {
    float t[2][4];
    for (int m = 0; m < 2; m++)
        for (int c = 0; c < 4; c++) {
            float s = 0.f;
            for (int b = 0; b < 32; b++) s += g_tp[m][b][c];
            t[m][c] = s;
        }
    float s0 = t[0][0] - 0.5f * t[0][1] + (1.f / 3.f) * t[0][2] - 0.25f * t[0][3];
    float s1 = t[1][0] - 0.5f * t[1][1] + (1.f / 3.f) * t[1][2] - 0.25f * t[1][3];
    float loss = (s0 + s1) * 0.5f / (float)NB;
    out[0] = -loss * (*plam);
}

// ---------------------------------------------------------------------------
// Launch
// ---------------------------------------------------------------------------
extern "C" void kernel_launch(void* const* d_in, const int* in_sizes, int n_in,
                              void* d_out, int out_size) {
    const float* z1    = (const float*)d_in[0];
    const float* z2    = (const float*)d_in[1];
    const float* p1    = (const float*)d_in[2];
    const float* p2    = (const float*)d_in[3];
    const float* W1    = (const float*)d_in[4];
    const float* gamma = (const float*)d_in[5];
    const float* beta  = (const float*)d_in[6];
    const float* W2    = (const float*)d_in[7];
    const float* b2    = (const float*)d_in[8];
    const float* plam  = (const float*)d_in[9];
    float* out = (float*)d_out;

    __half* w1t16; cudaGetSymbolAddress((void**)&w1t16, g_W1T16);
    __half* w2t16; cudaGetSymbolAddress((void**)&w2t16, g_W2T16);

    cudaFuncSetAttribute(k_gemm1, cudaFuncAttributeMaxDynamicSharedMemorySize, X3_DYN);
    cudaFuncSetAttribute(k_gemm2, cudaFuncAttributeMaxDynamicSharedMemorySize, X2_DYN);
    cudaFuncSetAttribute(k_gemmM, cudaFuncAttributeMaxDynamicSharedMemorySize, X3_DYN);

    // 0) prolog: z -> fp16; W1^T, W2^T -> fp16 (n-major for cp.async B tiles)
    k_cvtz<<<4096, 256>>>(z1, z2);
    k_transcvt<<<dim3(NE / 32, NH / 32), 256>>>(W1, w1t16, NE, NH);
    k_transcvt<<<dim3(NH / 32, NE / 32), 256>>>(W2, w2t16, NH, NE);
    // 1) H16 = z @ W1 (fp16 mma, 3-stage) + fused BN partial stats; finalize
    k_gemm1<<<dim3(NH / 128, NB / 128, 2), 256, X3_DYN>>>();
    k_bnfin<<<(2 * NH) / 256, 256>>>(gamma, beta);
    // 2) Q = relu(bn(H16)) @ W2 + b2
    k_gemm2<<<dim3(NE / 128, NB / 128, 2), 256, X2_DYN>>>(b2);
    // 3) norms; transpose+normalize p's and q's to fp16
    k_norms<<<dim3(NB / 8, 4), 256>>>(p1, p2);
    k_transnorm16<<<dim3(NB / 32, NE / 32, 4), 256>>>(p1, p2);
    // 4) M via split-K fp16 GEMM (3-stage) + deterministic reduce
    k_gemmM<<<dim3(NE / 128, NE / 128, 32), 256, X3_DYN>>>();
    k_Mred<<<dim3((NE * NE) / 256, 2), 256>>>(plam);
    // 5) M2, traces, final
    k_M2<<<dim3(NE / 64, NE / 64, 2), 256>>>();
    k_traces<<<dim3(32, 2), 256>>>();
    k_final<<<1, 1>>>(plam, out);
}